// round 3
// baseline (speedup 1.0000x reference)
#include <cuda_runtime.h>
#include <cstdint>

#define N_NODES 100000
#define N_EDGES 6400000
#define F 128
#define RCUT 5.0f
#define TN 16            // nodes per tile in transform kernel
#define TPB 128          // threads per block (one per output feature)
#define N_TILES (N_NODES / TN)   // 6250 exactly

// Scratch (static device allocations are allowed; cudaMalloc is not)
__device__ float  g_q[N_NODES];
__device__ float4 g_mu4[N_NODES];

// ---------------- packed f32x2 helpers (Blackwell FFMA2 path) ----------------
__device__ __forceinline__ unsigned long long pack2(float lo, float hi) {
    unsigned long long r;
    asm("mov.b64 %0, {%1, %2};" : "=l"(r) : "f"(lo), "f"(hi));
    return r;
}
__device__ __forceinline__ void unpack2(unsigned long long v, float& lo, float& hi) {
    asm("mov.b64 {%0, %1}, %2;" : "=f"(lo), "=f"(hi) : "l"(v));
}
__device__ __forceinline__ unsigned long long fma2(unsigned long long a,
                                                   unsigned long long b,
                                                   unsigned long long c) {
    unsigned long long d;
    asm("fma.rn.f32x2 %0, %1, %2, %3;" : "=l"(d) : "l"(a), "l"(b), "l"(c));
    return d;
}

__device__ __forceinline__ float silu_f(float a) {
    // a * sigmoid(a) = a / (1 + exp(-a)); MUFU-based, ~1e-6 rel err
    return __fdividef(a, 1.0f + __expf(-a));
}

// ---------------- zero scratch ----------------
__global__ void zero_kernel() {
    for (int i = blockIdx.x * blockDim.x + threadIdx.x; i < N_NODES;
         i += gridDim.x * blockDim.x) {
        g_mu4[i] = make_float4(0.f, 0.f, 0.f, 0.f);
    }
}

// ---------------- node transform: q = silu(silu(x@W1+b1)@W2+b2) ----------------
// Persistent blocks; W1 (64KB) cached in dynamic smem; x tile stored transposed
// [k][n] so ld.shared.v2.b64 gives node-pairs directly for fma.rn.f32x2.
__global__ __launch_bounds__(TPB, 3)
void transform_kernel(const float* __restrict__ x,
                      const float* __restrict__ W1,
                      const float* __restrict__ b1,
                      const float* __restrict__ W2,
                      const float* __restrict__ b2) {
    extern __shared__ float smem[];
    float* W1s = smem;                 // [F][F] row-major (k-major): W1s[k*F + j]
    float* xs  = smem + F * F;         // [F][TN]: xs[k*TN + n]
    __shared__ float red[4 * TN];      // per-warp partial sums for q-reduction

    const int tid  = threadIdx.x;
    const int lane = tid & 31;
    const int wid  = tid >> 5;

    // Stage W1 into smem (vectorized, coalesced; layout matches global row-major)
    {
        const float4* W14 = (const float4*)W1;
        float4* W1s4 = (float4*)W1s;
        #pragma unroll
        for (int i = tid; i < F * F / 4; i += TPB) W1s4[i] = W14[i];
    }
    const float myb1 = b1[tid];
    const float w2   = W2[tid];
    const float b2v  = b2[0];
    __syncthreads();

    const unsigned xs_sh = (unsigned)__cvta_generic_to_shared(xs);
    const unsigned w_sh  = (unsigned)__cvta_generic_to_shared(W1s) + tid * 4;

    for (int t = blockIdx.x; t < N_TILES; t += gridDim.x) {
        const int base = t * TN;

        // Load 16 node rows, store transposed into xs[k][n].
        {
            const int n = tid >> 3;             // 8 threads per node row
            const int c = (tid & 7) * 16;       // 16 contiguous floats each
            const float4* xr = (const float4*)(x + (size_t)(base + n) * F + c);
            #pragma unroll
            for (int v = 0; v < 4; v++) {
                float4 val = xr[v];
                int k0 = c + v * 4;
                xs[(k0 + 0) * TN + n] = val.x;
                xs[(k0 + 1) * TN + n] = val.y;
                xs[(k0 + 2) * TN + n] = val.z;
                xs[(k0 + 3) * TN + n] = val.w;
            }
        }
        __syncthreads();

        // Mainloop: acc[i] holds h for nodes (2i, 2i+1), feature j = tid
        unsigned long long acc[8];
        const unsigned long long binit = pack2(myb1, myb1);
        #pragma unroll
        for (int i = 0; i < 8; i++) acc[i] = binit;

        #pragma unroll 8
        for (int k = 0; k < F; k++) {
            float w;
            asm("ld.shared.f32 %0, [%1];" : "=f"(w) : "r"(w_sh + k * (F * 4)));
            unsigned long long wp = pack2(w, w);
            unsigned long long x0, x1, x2, x3, x4, x5, x6, x7;
            const unsigned a = xs_sh + k * (TN * 4);
            asm("ld.shared.v2.b64 {%0, %1}, [%2];"    : "=l"(x0), "=l"(x1) : "r"(a));
            asm("ld.shared.v2.b64 {%0, %1}, [%2+16];" : "=l"(x2), "=l"(x3) : "r"(a));
            asm("ld.shared.v2.b64 {%0, %1}, [%2+32];" : "=l"(x4), "=l"(x5) : "r"(a));
            asm("ld.shared.v2.b64 {%0, %1}, [%2+48];" : "=l"(x6), "=l"(x7) : "r"(a));
            acc[0] = fma2(x0, wp, acc[0]);
            acc[1] = fma2(x1, wp, acc[1]);
            acc[2] = fma2(x2, wp, acc[2]);
            acc[3] = fma2(x3, wp, acc[3]);
            acc[4] = fma2(x4, wp, acc[4]);
            acc[5] = fma2(x5, wp, acc[5]);
            acc[6] = fma2(x6, wp, acc[6]);
            acc[7] = fma2(x7, wp, acc[7]);
        }

        // silu(h) * W2[j], then reduce over the 128 features
        float pv[TN];
        #pragma unroll
        for (int i = 0; i < 8; i++) {
            float a0, a1;
            unpack2(acc[i], a0, a1);
            pv[2 * i + 0] = silu_f(a0) * w2;
            pv[2 * i + 1] = silu_f(a1) * w2;
        }
        #pragma unroll
        for (int i = 0; i < TN; i++) {
            float v = pv[i];
            #pragma unroll
            for (int off = 16; off > 0; off >>= 1)
                v += __shfl_xor_sync(0xffffffffu, v, off);
            pv[i] = v;
        }
        if (lane == 0) {
            #pragma unroll
            for (int i = 0; i < TN; i++) red[wid * TN + i] = pv[i];
        }
        __syncthreads();
        if (tid < TN) {
            float s = red[tid] + red[TN + tid] + red[2 * TN + tid] +
                      red[3 * TN + tid] + b2v;
            g_q[base + tid] = silu_f(s);
        }
        __syncthreads();  // protect xs/red before next tile
    }
}

// ---------------- edge phase: mu_ij = vij * q[src] * c(rij), scatter-add ----------------
// 4 edges per thread -> vectorized float4/int4 loads; one red.v4 per edge.
__global__ void edge_kernel(const float* __restrict__ rij,
                            const float* __restrict__ vij,
                            const int* __restrict__ src,
                            const int* __restrict__ dst) {
    const int t = blockIdx.x * blockDim.x + threadIdx.x;
    if (t * 4 >= N_EDGES) return;

    float4 r4 = ((const float4*)rij)[t];
    int4   s4 = ((const int4*)src)[t];
    int4   d4 = ((const int4*)dst)[t];
    float4 v0 = ((const float4*)vij)[t * 3 + 0];
    float4 v1 = ((const float4*)vij)[t * 3 + 1];
    float4 v2 = ((const float4*)vij)[t * 3 + 2];

    float r[4]  = {r4.x, r4.y, r4.z, r4.w};
    int   sn[4] = {s4.x, s4.y, s4.z, s4.w};
    int   dn[4] = {d4.x, d4.y, d4.z, d4.w};
    // edge components: e0=(v0.x,v0.y,v0.z) e1=(v0.w,v1.x,v1.y) e2=(v1.z,v1.w,v2.x) e3=(v2.y,v2.z,v2.w)
    float ex[4] = {v0.x, v0.w, v1.z, v2.y};
    float ey[4] = {v0.y, v1.x, v1.w, v2.z};
    float ez[4] = {v0.z, v1.y, v2.x, v2.w};

    #pragma unroll
    for (int i = 0; i < 4; i++) {
        float c = 0.0f;
        if (r[i] < RCUT) c = 0.5f * (cospif(r[i] * (1.0f / RCUT)) + 1.0f);
        float s = __ldg(&g_q[sn[i]]) * c;
        unsigned long long addr = (unsigned long long)(&g_mu4[dn[i]]);
        asm volatile("red.global.add.v4.f32 [%0], {%1, %2, %3, %4};"
                     :: "l"(addr), "f"(ex[i] * s), "f"(ey[i] * s),
                        "f"(ez[i] * s), "f"(0.0f)
                     : "memory");
    }
}

// ---------------- pack float4 scratch -> [N,3] output ----------------
__global__ void copy_kernel(float* __restrict__ out) {
    int i = blockIdx.x * blockDim.x + threadIdx.x;
    if (i < N_NODES) {
        float4 m = g_mu4[i];
        out[3 * i + 0] = m.x;
        out[3 * i + 1] = m.y;
        out[3 * i + 2] = m.z;
    }
}

extern "C" void kernel_launch(void* const* d_in, const int* in_sizes, int n_in,
                              void* d_out, int out_size) {
    const float* x   = (const float*)d_in[0];
    const float* rij = (const float*)d_in[1];
    const float* vij = (const float*)d_in[2];
    const int*   src = (const int*)d_in[3];
    const int*   dst = (const int*)d_in[4];
    const float* W1  = (const float*)d_in[5];
    const float* b1  = (const float*)d_in[6];
    const float* W2  = (const float*)d_in[7];
    const float* b2  = (const float*)d_in[8];
    float* out = (float*)d_out;

    const int smem_bytes = (F * F + F * TN) * sizeof(float);  // 72 KB
    cudaFuncSetAttribute(transform_kernel,
                         cudaFuncAttributeMaxDynamicSharedMemorySize, smem_bytes);

    zero_kernel<<<392, 256>>>();
    transform_kernel<<<444, TPB, smem_bytes>>>(x, W1, b1, W2, b2);
    edge_kernel<<<(N_EDGES / 4 + 255) / 256, 256>>>(rij, vij, src, dst);
    copy_kernel<<<(N_NODES + 255) / 256, 256>>>(out);
}

// round 14
// speedup vs baseline: 1.3140x; 1.3140x over previous
#include <cuda_runtime.h>
#include <cuda_bf16.h>
#include <cstdint>

#define N_NODES 100000
#define N_EDGES 6400000
#define F 128
#define RCUT 5.0f

// ---------------- transform (mma.sync) config ----------------
#define TM 128                       // nodes per block tile
#define NT_MMA ((N_NODES + TM - 1) / TM)   // 782
#define MGRID 148
#define MTPB 256                     // 8 warps
#define PADK 136                     // bf16 row pitch (272B): bank-conflict-free frags
#define ROWB (PADK * 2)              // 272 bytes

// smem byte offsets
#define SM_B1  0                     // 128 f32
#define SM_W2  512                   // 128 f32
#define SM_WHI 1024                  // W1^T hi [j=128][PADK] bf16
#define SM_WLO (SM_WHI + F * ROWB)   // 35840
#define SM_XHI (SM_WLO + F * ROWB)   // 70656
#define SM_XLO (SM_XHI + TM * ROWB)  // 105472
#define SM_TOT (SM_XLO + TM * ROWB)  // 140288 bytes

// Scratch (static device arrays; cudaMalloc is forbidden)
__device__ float  g_q[N_NODES];
__device__ float4 g_mu4[N_NODES];

__device__ __forceinline__ float silu_f(float a) {
    return __fdividef(a, 1.0f + __expf(-a));
}
__device__ __forceinline__ unsigned packbf(float a, float b) {
    return (unsigned)__bfloat16_as_ushort(__float2bfloat16(a)) |
           ((unsigned)__bfloat16_as_ushort(__float2bfloat16(b)) << 16);
}
__device__ __forceinline__ void mma16816(float* d, const unsigned* a, const unsigned* b) {
    asm volatile(
        "mma.sync.aligned.m16n8k16.row.col.f32.bf16.bf16.f32 "
        "{%0,%1,%2,%3}, {%4,%5,%6,%7}, {%8,%9}, {%0,%1,%2,%3};"
        : "+f"(d[0]), "+f"(d[1]), "+f"(d[2]), "+f"(d[3])
        : "r"(a[0]), "r"(a[1]), "r"(a[2]), "r"(a[3]), "r"(b[0]), "r"(b[1]));
}

// ---------------- dummy: shifts ncu capture index so -s 5 lands on edge_kernel ----------------
__global__ void dummy_kernel() {}

// ---------------- zero scratch ----------------
__global__ void zero_kernel() {
    for (int i = blockIdx.x * blockDim.x + threadIdx.x; i < N_NODES;
         i += gridDim.x * blockDim.x)
        g_mu4[i] = make_float4(0.f, 0.f, 0.f, 0.f);
}

// ---------------- node transform via mma.sync bf16 3-pass split ----------------
// q = silu( sum_j silu((x@W1)_j + b1_j) * W2_j + b2 ),  x@W1 ~= xh@wh + xh@wl + xl@wh
__global__ __launch_bounds__(MTPB, 1)
void transform_mma(const float* __restrict__ x,
                   const float* __restrict__ W1,
                   const float* __restrict__ b1,
                   const float* __restrict__ W2,
                   const float* __restrict__ b2) {
    extern __shared__ char smem[];
    const int tid  = threadIdx.x;
    const int wid  = tid >> 5;           // 0..7
    const int lane = tid & 31;
    const int g    = lane >> 2;          // 0..7
    const int t4   = lane & 3;           // 0..3

    // ---- stage b1, W2 (f32) and W1^T hi/lo (bf16, padded rows) ----
    if (tid < F) {
        ((float*)(smem + SM_B1))[tid] = b1[tid];
        ((float*)(smem + SM_W2))[tid] = W2[tid];
    }
    const float b2v = b2[0];
    for (int idx = tid; idx < F * F; idx += MTPB) {
        int k = idx >> 7, j = idx & 127;        // consecutive tid -> consecutive j
        float w = W1[k * F + j];
        __nv_bfloat16 h = __float2bfloat16(w);
        float l = w - __bfloat162float(h);
        *(__nv_bfloat16*)(smem + SM_WHI + j * ROWB + k * 2) = h;
        *(__nv_bfloat16*)(smem + SM_WLO + j * ROWB + k * 2) = __float2bfloat16(l);
    }
    __syncthreads();

    const float* B1s = (const float*)(smem + SM_B1);
    const float* W2s = (const float*)(smem + SM_W2);

    for (int t = blockIdx.x; t < NT_MMA; t += MGRID) {
        const int base = t * TM;

        // ---- stage x tile [TM][F] -> bf16 hi/lo, padded rows ----
        // thread: row = tid>>1, k-half = (tid&1)*64; 16 float4 each
        {
            int row = tid >> 1;
            int kh  = (tid & 1) * 64;
            int gr  = base + row;
            const float4* xr = (const float4*)(x + (size_t)gr * F + kh);
            #pragma unroll
            for (int v = 0; v < 16; v++) {
                float4 val = (gr < N_NODES) ? xr[v] : make_float4(0.f, 0.f, 0.f, 0.f);
                float hx = __bfloat162float(__float2bfloat16(val.x));
                float hy = __bfloat162float(__float2bfloat16(val.y));
                float hz = __bfloat162float(__float2bfloat16(val.z));
                float hw = __bfloat162float(__float2bfloat16(val.w));
                uint2 hi = make_uint2(packbf(val.x, val.y), packbf(val.z, val.w));
                uint2 lo = make_uint2(packbf(val.x - hx, val.y - hy),
                                      packbf(val.z - hz, val.w - hw));
                int off = row * ROWB + (kh + v * 4) * 2;
                *(uint2*)(smem + SM_XHI + off) = hi;
                *(uint2*)(smem + SM_XLO + off) = lo;
            }
        }
        __syncthreads();

        // ---- A fragments: rows m0+g / m0+g+8, 8 k-chunks, hi+lo ----
        const int m0 = wid * 16;
        unsigned ahi[8][4], alo[8][4];
        {
            int ra = (m0 + g) * ROWB, rb = (m0 + g + 8) * ROWB;
            #pragma unroll
            for (int kc = 0; kc < 8; kc++) {
                int c0 = (kc * 16 + 2 * t4) * 2;   // byte offset of col pair
                ahi[kc][0] = *(const unsigned*)(smem + SM_XHI + ra + c0);
                ahi[kc][1] = *(const unsigned*)(smem + SM_XHI + rb + c0);
                ahi[kc][2] = *(const unsigned*)(smem + SM_XHI + ra + c0 + 16);
                ahi[kc][3] = *(const unsigned*)(smem + SM_XHI + rb + c0 + 16);
                alo[kc][0] = *(const unsigned*)(smem + SM_XLO + ra + c0);
                alo[kc][1] = *(const unsigned*)(smem + SM_XLO + rb + c0);
                alo[kc][2] = *(const unsigned*)(smem + SM_XLO + ra + c0 + 16);
                alo[kc][3] = *(const unsigned*)(smem + SM_XLO + rb + c0 + 16);
            }
        }

        // ---- 16 j-tiles of 8: GEMM + fused epilogue ----
        float qa = 0.0f, qb = 0.0f;     // row m0+g, row m0+g+8 partial q-sums
        #pragma unroll 4
        for (int jt = 0; jt < 16; jt++) {
            float acc[4] = {0.f, 0.f, 0.f, 0.f};
            const int jrow = (jt * 8 + g) * ROWB;   // B n-index = g
            #pragma unroll
            for (int kc = 0; kc < 8; kc++) {
                int c0 = (kc * 16 + 2 * t4) * 2;
                unsigned bhi[2], blo[2];
                bhi[0] = *(const unsigned*)(smem + SM_WHI + jrow + c0);
                bhi[1] = *(const unsigned*)(smem + SM_WHI + jrow + c0 + 16);
                blo[0] = *(const unsigned*)(smem + SM_WLO + jrow + c0);
                blo[1] = *(const unsigned*)(smem + SM_WLO + jrow + c0 + 16);
                mma16816(acc, ahi[kc], bhi);
                mma16816(acc, ahi[kc], blo);
                mma16816(acc, alo[kc], bhi);
            }
            // acc: D[m0+g][j0], D[m0+g][j0+1], D[m0+g+8][j0], D[m0+g+8][j0+1]
            int j0 = jt * 8 + 2 * t4;
            qa += silu_f(acc[0] + B1s[j0])     * W2s[j0]
                + silu_f(acc[1] + B1s[j0 + 1]) * W2s[j0 + 1];
            qb += silu_f(acc[2] + B1s[j0])     * W2s[j0]
                + silu_f(acc[3] + B1s[j0 + 1]) * W2s[j0 + 1];
        }
        // reduce over t4 (lanes 4g..4g+3)
        qa += __shfl_xor_sync(0xffffffffu, qa, 1);
        qa += __shfl_xor_sync(0xffffffffu, qa, 2);
        qb += __shfl_xor_sync(0xffffffffu, qb, 1);
        qb += __shfl_xor_sync(0xffffffffu, qb, 2);
        if (t4 == 0) {
            int na = base + m0 + g, nb = na + 8;
            if (na < N_NODES) g_q[na] = silu_f(qa + b2v);
            if (nb < N_NODES) g_q[nb] = silu_f(qb + b2v);
        }
        __syncthreads();   // protect X tiles before next staging
    }
}

// ---------------- edge phase: mu_ij = vij * q[src] * c(rij), scatter-add ----------------
// 4 edges/thread; scatter = red.v2 (x,y) + scalar red (z): 3 useful 4B atomic lanes.
__global__ void edge_kernel(const float* __restrict__ rij,
                            const float* __restrict__ vij,
                            const int* __restrict__ src,
                            const int* __restrict__ dst) {
    const int t = blockIdx.x * blockDim.x + threadIdx.x;
    if (t * 4 >= N_EDGES) return;

    float4 r4 = ((const float4*)rij)[t];
    int4   s4 = ((const int4*)src)[t];
    int4   d4 = ((const int4*)dst)[t];
    float4 v0 = ((const float4*)vij)[t * 3 + 0];
    float4 v1 = ((const float4*)vij)[t * 3 + 1];
    float4 v2 = ((const float4*)vij)[t * 3 + 2];

    float r[4]  = {r4.x, r4.y, r4.z, r4.w};
    int   sn[4] = {s4.x, s4.y, s4.z, s4.w};
    int   dn[4] = {d4.x, d4.y, d4.z, d4.w};
    float ex[4] = {v0.x, v0.w, v1.z, v2.y};
    float ey[4] = {v0.y, v1.x, v1.w, v2.z};
    float ez[4] = {v0.z, v1.y, v2.x, v2.w};

    #pragma unroll
    for (int i = 0; i < 4; i++) {
        float c = 0.0f;
        if (r[i] < RCUT) c = 0.5f * (cospif(r[i] * (1.0f / RCUT)) + 1.0f);
        float s = __ldg(&g_q[sn[i]]) * c;
        unsigned long long addr = (unsigned long long)(&g_mu4[dn[i]]);
        asm volatile("red.global.add.v2.f32 [%0], {%1, %2};"
                     :: "l"(addr), "f"(ex[i] * s), "f"(ey[i] * s) : "memory");
        asm volatile("red.global.add.f32 [%0], %1;"
                     :: "l"(addr + 8), "f"(ez[i] * s) : "memory");
    }
}

// ---------------- pack float4 scratch -> [N,3] output ----------------
__global__ void copy_kernel(float* __restrict__ out) {
    int i = blockIdx.x * blockDim.x + threadIdx.x;
    if (i < N_NODES) {
        float4 m = g_mu4[i];
        out[3 * i + 0] = m.x;
        out[3 * i + 1] = m.y;
        out[3 * i + 2] = m.z;
    }
}

extern "C" void kernel_launch(void* const* d_in, const int* in_sizes, int n_in,
                              void* d_out, int out_size) {
    const float* x   = (const float*)d_in[0];
    const float* rij = (const float*)d_in[1];
    const float* vij = (const float*)d_in[2];
    const int*   src = (const int*)d_in[3];
    const int*   dst = (const int*)d_in[4];
    const float* W1  = (const float*)d_in[5];
    const float* b1  = (const float*)d_in[6];
    const float* W2  = (const float*)d_in[7];
    const float* b2  = (const float*)d_in[8];
    float* out = (float*)d_out;

    cudaFuncSetAttribute(transform_mma,
                         cudaFuncAttributeMaxDynamicSharedMemorySize, SM_TOT);

    dummy_kernel<<<1, 32>>>();   // capture-index shim: -s 5 (+2 offset) -> edge_kernel
    zero_kernel<<<392, 256>>>();
    transform_mma<<<MGRID, MTPB, SM_TOT>>>(x, W1, b1, W2, b2);
    edge_kernel<<<(N_EDGES / 4 + 255) / 256, 256>>>(rij, vij, src, dst);
    copy_kernel<<<(N_NODES + 255) / 256, 256>>>(out);
}